// round 13
// baseline (speedup 1.0000x reference)
#include <cuda_runtime.h>
#include <cuda_fp16.h>
#include <math.h>
#include <cstdint>

#define BB 256
#define TT 256
#define CC 1024
#define DD 64
#define BT (BB*TT)

// Scratch: Q, K, V as half (8 MB each) + transposed W as half (384 KB)
__device__ __half g_qh[BT*DD];
__device__ __half g_kh[BT*DD];
__device__ __half g_vh[BT*DD];
__device__ __half g_wth[192*1024];   // K-major: rows 0-63 Wq^T, 64-127 Wk^T, 128-191 Wv^T

// ===================== PTX helpers (sm_80+ PTX, ok on compute_103) =========
__device__ __forceinline__ void mma_f16_16n8k16(
    float d[4], const uint32_t a[4], const uint32_t b[2])
{
    asm volatile(
        "mma.sync.aligned.m16n8k16.row.col.f32.f16.f16.f32 "
        "{%0,%1,%2,%3}, {%4,%5,%6,%7}, {%8,%9}, {%0,%1,%2,%3};"
        : "+f"(d[0]), "+f"(d[1]), "+f"(d[2]), "+f"(d[3])
        : "r"(a[0]), "r"(a[1]), "r"(a[2]), "r"(a[3]),
          "r"(b[0]), "r"(b[1]));
}

__device__ __forceinline__ void ldmatrix_x4(uint32_t r[4], uint32_t addr) {
    asm volatile("ldmatrix.sync.aligned.m8n8.x4.shared.b16 {%0,%1,%2,%3}, [%4];"
        : "=r"(r[0]), "=r"(r[1]), "=r"(r[2]), "=r"(r[3]) : "r"(addr));
}

__device__ __forceinline__ void ldmatrix_x4_trans(uint32_t r[4], uint32_t addr) {
    asm volatile("ldmatrix.sync.aligned.m8n8.x4.trans.shared.b16 {%0,%1,%2,%3}, [%4];"
        : "=r"(r[0]), "=r"(r[1]), "=r"(r[2]), "=r"(r[3]) : "r"(addr));
}

__device__ __forceinline__ void cp_async16(uint32_t dst, const void* src) {
    asm volatile("cp.async.cg.shared.global [%0], [%1], 16;"
        :: "r"(dst), "l"(src) : "memory");
}
#define CP_COMMIT() asm volatile("cp.async.commit_group;" ::: "memory")
#define CP_WAIT1()  asm volatile("cp.async.wait_group 1;" ::: "memory")
#define CP_WAIT0()  asm volatile("cp.async.wait_group 0;" ::: "memory")

__device__ __forceinline__ uint32_t smem_u32(const void* p) {
    uint32_t a;
    asm("{ .reg .u64 t; cvta.to.shared.u64 t, %1; cvt.u32.u64 %0, t; }"
        : "=r"(a) : "l"(p));
    return a;
}

__device__ __forceinline__ uint32_t pack_h2(float a, float b) {
    half2 h = __floats2half2_rn(a, b);
    return *(uint32_t*)&h;
}

// ===================== Kernel 0: coalesced tile-transpose of W =============
__global__ __launch_bounds__(256) void transpose_w_kernel(
    const float* __restrict__ Wq, const float* __restrict__ Wk,
    const float* __restrict__ Wv)
{
    __shared__ float tile[64][65];
    const int m  = blockIdx.x >> 4;          // 0..2
    const int kt = blockIdx.x & 15;          // 0..15
    const float* W = (m == 0) ? Wq : (m == 1) ? Wk : Wv;

    const int r   = threadIdx.x >> 2;        // 0..63
    const int seg = threadIdx.x & 3;         // 0..3 (16 floats each)
    #pragma unroll
    for (int l = 0; l < 4; l++) {
        float4 v = *(const float4*)&W[(size_t)(kt * 64 + r) * 64 + seg * 16 + l * 4];
        tile[r][seg * 16 + l * 4 + 0] = v.x;
        tile[r][seg * 16 + l * 4 + 1] = v.y;
        tile[r][seg * 16 + l * 4 + 2] = v.z;
        tile[r][seg * 16 + l * 4 + 3] = v.w;
    }
    __syncthreads();

    const int n = r;
    uint32_t u[8];
    #pragma unroll
    for (int i = 0; i < 8; i++)
        u[i] = pack_h2(tile[seg * 16 + 2 * i][n], tile[seg * 16 + 2 * i + 1][n]);
    char* dst = (char*)&g_wth[(size_t)(m * 64 + n) * 1024 + kt * 64 + seg * 16];
    *(uint4*)dst        = make_uint4(u[0], u[1], u[2], u[3]);
    *(uint4*)(dst + 16) = make_uint4(u[4], u[5], u[6], u[7]);
}

// ===================== Kernel A: QKV via fp16 mma, 1-sync pipeline =========
// 1024 CTAs x 256 thr (8 warps = 2 M x 4 N), 2 CTAs/SM. CTA tile 64x192,
// warp tile 32x48. 16 K-chunks of 64.
// A (x): LDG + cvt + STS, double-buffered, staged 1 chunk ahead, LDG 2 ahead.
// B (g_wth): cp.async, TRIPLE-buffered (target never aliases readers) ->
// exactly ONE __syncthreads per chunk. All memory issued before the mma block.

#define STRH 72
#define QA_BYTES (64*STRH*2)                   // 9216
#define QB_BYTES (192*STRH*2)                  // 27648
#define QB_BASE  (2*QA_BYTES)                  // 18432
#define QKV_SMEM (QB_BASE + 3*QB_BYTES)        // 101376

__global__ __launch_bounds__(256, 2) void qkv_mma_kernel(const float* __restrict__ x)
{
    extern __shared__ __half smh[];
    const uint32_t sbase = smem_u32(smh);
    const int tid    = threadIdx.x;
    const int lane   = tid & 31;
    const int wid    = tid >> 5;
    const int warp_m = wid >> 2;
    const int warp_n = wid & 3;
    const int row0   = blockIdx.x * 64;

    const int lr = lane >> 2;
    const int lc = lane & 3;

    float acc[2][6][4];
    #pragma unroll
    for (int mt = 0; mt < 2; mt++)
        #pragma unroll
        for (int nt = 0; nt < 6; nt++)
            #pragma unroll
            for (int i = 0; i < 4; i++) acc[mt][nt][i] = 0.f;

    const int ar   = tid >> 2;        // 0..63
    const int aseg = tid & 3;         // 16-float segment

    float4 ra[4];
    auto ldg_a = [&](int c) {
        const float* src = &x[(size_t)(row0 + ar) * CC + c * 64 + aseg * 16];
        #pragma unroll
        for (int l = 0; l < 4; l++) ra[l] = *(const float4*)(src + l * 4);
    };
    auto sts_a = [&](uint32_t bufoff) {
        char* dst = (char*)smh + bufoff + ((uint32_t)(ar * STRH + aseg * 16)) * 2;
        uint4 u0 = make_uint4(pack_h2(ra[0].x, ra[0].y), pack_h2(ra[0].z, ra[0].w),
                              pack_h2(ra[1].x, ra[1].y), pack_h2(ra[1].z, ra[1].w));
        uint4 u1 = make_uint4(pack_h2(ra[2].x, ra[2].y), pack_h2(ra[2].z, ra[2].w),
                              pack_h2(ra[3].x, ra[3].y), pack_h2(ra[3].z, ra[3].w));
        *(uint4*)dst = u0;
        *(uint4*)(dst + 16) = u1;
    };
    auto cp_b = [&](int c, int bi) {
        const uint32_t dst0 = sbase + QB_BASE + (uint32_t)bi * QB_BYTES;
        #pragma unroll
        for (int l = 0; l < 6; l++) {
            int idx = tid + l * 256;
            int n   = idx >> 3;
            int sg  = idx & 7;
            cp_async16(dst0 + (uint32_t)(n * STRH + sg * 8) * 2,
                       &g_wth[(size_t)n * 1024 + c * 64 + sg * 8]);
        }
    };

    const uint32_t aoff =
        ((uint32_t)(warp_m * 32 + (lane & 7) + ((lane >> 3) & 1) * 8) * STRH
         + ((lane >> 4) & 1) * 8) * 2;
    const uint32_t boff =
        ((uint32_t)(warp_n * 48 + (lane & 7) + ((lane >> 4) & 1) * 8) * STRH
         + ((lane >> 3) & 1) * 8) * 2;

    // prologue: chunk0 A in smem; chunk1 A in regs; B0,B1 in flight
    ldg_a(0); sts_a(0);
    ldg_a(1);
    cp_b(0, 0); CP_COMMIT();
    cp_b(1, 1); CP_COMMIT();

    for (int c = 0; c < 16; c++) {
        CP_WAIT1();            // B(c) landed (B(c+1) may still be in flight)
        __syncthreads();       // all warps done with iter c-1 reads; B(c)+A(c) visible

        // ---- issue all memory for the future FIRST ----
        if (c + 1 < 16) sts_a((uint32_t)(((c + 1) & 1) * QA_BYTES));
        if (c + 2 < 16) {
            ldg_a(c + 2);
            cp_b(c + 2, (c + 2) % 3);
        }
        CP_COMMIT();           // exactly one group per iteration (may be empty)

        // ---- compute chunk c ----
        const uint32_t abase = sbase + (uint32_t)((c & 1) * QA_BYTES) + aoff;
        const uint32_t bbase = sbase + QB_BASE + (uint32_t)((c % 3) * QB_BYTES) + boff;

        #pragma unroll
        for (int ks = 0; ks < 4; ks++) {
            uint32_t af[2][4];
            #pragma unroll
            for (int mt = 0; mt < 2; mt++)
                ldmatrix_x4(af[mt], abase + mt * (16 * STRH * 2) + ks * 32);
            uint32_t bf[12];
            #pragma unroll
            for (int j = 0; j < 3; j++)
                ldmatrix_x4(&bf[j * 4], bbase + j * (16 * STRH * 2) + ks * 32);
            #pragma unroll
            for (int mt = 0; mt < 2; mt++)
                #pragma unroll
                for (int nt = 0; nt < 6; nt++)
                    mma_f16_16n8k16(acc[mt][nt], af[mt],
                                    &bf[(nt >> 1) * 4 + (nt & 1) * 2]);
        }
    }

    // epilogue: convert to half (rn), scatter to g_qh / g_kh / g_vh
    #pragma unroll
    for (int mt = 0; mt < 2; mt++) {
        int rg = row0 + warp_m * 32 + mt * 16 + lr;
        #pragma unroll
        for (int nt = 0; nt < 6; nt++) {
            int ng = warp_n * 48 + nt * 8 + lc * 2;
            int m  = ng >> 6;
            int d  = ng & 63;
            __half* base = (m == 0) ? g_qh : (m == 1) ? g_kh : g_vh;
            *(uint32_t*)&base[(size_t)rg * DD + d] =
                pack_h2(acc[mt][nt][0], acc[mt][nt][1]);
            *(uint32_t*)&base[(size_t)(rg + 8) * DD + d] =
                pack_h2(acc[mt][nt][2], acc[mt][nt][3]);
        }
    }
}

// ===================== Kernel B: attention, one CTA per batch (R12) ========
#define KSTR 72
#define SKB  0
#define SVB  (256*KSTR*2)                  // 36864
#define SOB  (2*256*KSTR*2)                // 73728
#define SUMB (SOB + 64*66*4)               // 90624
#define ATT_SMEM (SUMB + 512)              // 91136
#define SO_STRIDE 66

__global__ __launch_bounds__(256, 2) void attn_kernel(float* __restrict__ out)
{
    extern __shared__ __half smh[];
    const uint32_t sbase = smem_u32(smh);
    float* sO   = (float*)((char*)smh + SOB);
    float* sRed = (float*)((char*)smh + SUMB);   // 128 floats: row sums

    const int tid  = threadIdx.x;
    const int wid  = tid >> 5;
    const int lane = tid & 31;
    const int wm   = wid >> 1;          // 0..3: 16 q-rows each
    const int wn   = wid & 1;           // 0..1: 128 keys each
    const int lr   = lane >> 2;
    const int lc   = lane & 3;

    const int bb = blockIdx.x;          // batch

    // ---- stage full K, V once ----
    const __half* kb = g_kh + (size_t)bb * TT * DD;
    const __half* vb = g_vh + (size_t)bb * TT * DD;
    #pragma unroll
    for (int l = 0; l < 8; l++) {
        int idx = tid + l * 256;
        int s   = idx >> 3;
        int sg  = idx & 7;
        cp_async16(sbase + SKB + (uint32_t)(s * KSTR + sg * 8) * 2,
                   &kb[s * DD + sg * 8]);
        cp_async16(sbase + SVB + (uint32_t)(s * KSTR + sg * 8) * 2,
                   &vb[s * DD + sg * 8]);
    }
    CP_COMMIT();

    const uint32_t kbase = sbase + SKB +
        ((uint32_t)(wn * 128 + (lane & 7) + ((lane >> 4) & 1) * 8) * KSTR
         + ((lane >> 3) & 1) * 8) * 2;
    const uint32_t vbase = sbase + SVB +
        ((uint32_t)(wn * 128 + (lane & 7) + ((lane >> 3) & 1) * 8) * KSTR
         + ((lane >> 4) & 1) * 8) * 2;

    const float SC = 0.03125f;          // C^-0.5

    bool staged = false;
    for (int t = 0; t < 4; t++) {
        const int q0 = t * 64;
        const int rg0 = q0 + wm * 16 + lr;
        const int rg1 = rg0 + 8;

        uint32_t qf[4][4];
        {
            const uint32_t* q32 =
                (const uint32_t*)(g_qh + (size_t)(bb * TT + q0 + wm * 16 + lr) * DD);
            const uint32_t* q32b = q32 + 8 * 32;
            #pragma unroll
            for (int ks = 0; ks < 4; ks++) {
                qf[ks][0] = q32 [ks * 8 + lc];
                qf[ks][1] = q32b[ks * 8 + lc];
                qf[ks][2] = q32 [ks * 8 + lc + 4];
                qf[ks][3] = q32b[ks * 8 + lc + 4];
            }
        }
        if (!staged) {
            CP_WAIT0();
            __syncthreads();
            staged = true;
        }

        const int ntv = min(16, max(0, (q0 + 64 - wn * 128) / 8));
        const int ng2 = ntv >> 1;

        uint32_t pf[8][4];
        float srow[2] = {0.f, 0.f};
        #pragma unroll
        for (int g = 0; g < 8; g++) {
            if (g >= ng2) break;
            float s0[4] = {0.f, 0.f, 0.f, 0.f};
            float s1[4] = {0.f, 0.f, 0.f, 0.f};
            #pragma unroll
            for (int ks = 0; ks < 4; ks++) {
                uint32_t bf[4];
                ldmatrix_x4(bf, kbase + g * (16 * KSTR * 2) + ks * 32);
                mma_f16_16n8k16(s0, qf[ks], &bf[0]);
                mma_f16_16n8k16(s1, qf[ks], &bf[2]);
            }
            const int cb = wn * 128 + g * 16 + 2 * lc;
            float e00 = (cb     <= rg0) ? __expf(s0[0] * SC) : 0.f;
            float e01 = (cb + 1 <= rg0) ? __expf(s0[1] * SC) : 0.f;
            float e02 = (cb     <= rg1) ? __expf(s0[2] * SC) : 0.f;
            float e03 = (cb + 1 <= rg1) ? __expf(s0[3] * SC) : 0.f;
            float e10 = (cb + 8 <= rg0) ? __expf(s1[0] * SC) : 0.f;
            float e11 = (cb + 9 <= rg0) ? __expf(s1[1] * SC) : 0.f;
            float e12 = (cb + 8 <= rg1) ? __expf(s1[2] * SC) : 0.f;
            float e13 = (cb + 9 <= rg1) ? __expf(s1[3] * SC) : 0.f;
            srow[0] += e00 + e01 + e10 + e11;
            srow[1] += e02 + e03 + e12 + e13;
            pf[g][0] = pack_h2(e00, e01);
            pf[g][1] = pack_h2(e02, e03);
            pf[g][2] = pack_h2(e10, e11);
            pf[g][3] = pack_h2(e12, e13);
        }

        #pragma unroll
        for (int off = 1; off <= 2; off <<= 1) {
            srow[0] += __shfl_xor_sync(0xFFFFFFFF, srow[0], off);
            srow[1] += __shfl_xor_sync(0xFFFFFFFF, srow[1], off);
        }
        if (lc == 0) {
            sRed[wn * 64 + wm * 16 + lr]     = srow[0];
            sRed[wn * 64 + wm * 16 + lr + 8] = srow[1];
        }
        __syncthreads();

        const float inv0 = 1.f / (sRed[wm * 16 + lr]     + sRed[64 + wm * 16 + lr]);
        const float inv1 = 1.f / (sRed[wm * 16 + lr + 8] + sRed[64 + wm * 16 + lr + 8]);

        float oacc[8][4];
        #pragma unroll
        for (int nt = 0; nt < 8; nt++)
            #pragma unroll
            for (int i = 0; i < 4; i++) oacc[nt][i] = 0.f;

        #pragma unroll
        for (int g = 0; g < 8; g++) {
            if (g >= ng2) break;
            #pragma unroll
            for (int pr = 0; pr < 4; pr++) {
                uint32_t bf[4];
                ldmatrix_x4_trans(bf, vbase + g * (16 * KSTR * 2) + pr * 32);
                mma_f16_16n8k16(oacc[2*pr],     pf[g], &bf[0]);
                mma_f16_16n8k16(oacc[2*pr + 1], pf[g], &bf[2]);
            }
        }

        if (wn == 0) {
            #pragma unroll
            for (int nt = 0; nt < 8; nt++) {
                float* o0 = sO + (wm * 16 + lr) * SO_STRIDE + nt * 8 + 2 * lc;
                *(float2*)o0 = make_float2(oacc[nt][0], oacc[nt][1]);
                float* o1 = o0 + 8 * SO_STRIDE;
                *(float2*)o1 = make_float2(oacc[nt][2], oacc[nt][3]);
            }
        }
        __syncthreads();
        if (wn == 1) {
            const size_t orow = (size_t)(bb * TT + q0 + wm * 16 + lr) * DD;
            #pragma unroll
            for (int nt = 0; nt < 8; nt++) {
                const float* o0 = sO + (wm * 16 + lr) * SO_STRIDE + nt * 8 + 2 * lc;
                const float* o1 = o0 + 8 * SO_STRIDE;
                float2 r0v = make_float2((oacc[nt][0] + o0[0]) * inv0,
                                         (oacc[nt][1] + o0[1]) * inv0);
                float2 r1v = make_float2((oacc[nt][2] + o1[0]) * inv1,
                                         (oacc[nt][3] + o1[1]) * inv1);
                *(float2*)&out[orow + nt * 8 + 2 * lc] = r0v;
                *(float2*)&out[orow + 8 * DD + nt * 8 + 2 * lc] = r1v;
            }
        }
        __syncthreads();
    }
}

// ---------------------------------------------------------------------------
extern "C" void kernel_launch(void* const* d_in, const int* in_sizes, int n_in,
                              void* d_out, int out_size)
{
    (void)in_sizes; (void)n_in; (void)out_size;
    const float* x  = (const float*)d_in[0];
    const float* Wq = (const float*)d_in[1];
    const float* Wk = (const float*)d_in[2];
    const float* Wv = (const float*)d_in[3];
    float* out = (float*)d_out;

    cudaFuncSetAttribute(qkv_mma_kernel,
                         cudaFuncAttributeMaxDynamicSharedMemorySize, QKV_SMEM);
    cudaFuncSetAttribute(attn_kernel,
                         cudaFuncAttributeMaxDynamicSharedMemorySize, ATT_SMEM);

    transpose_w_kernel<<<48, 256>>>(Wq, Wk, Wv);
    qkv_mma_kernel<<<BT / 64, 256, QKV_SMEM>>>(x);
    attn_kernel<<<BB, 256, ATT_SMEM>>>(out);
}

// round 14
// speedup vs baseline: 1.1057x; 1.1057x over previous
#include <cuda_runtime.h>
#include <cuda_fp16.h>
#include <math.h>
#include <cstdint>

#define BB 256
#define TT 256
#define CC 1024
#define DD 64
#define BT (BB*TT)

// Scratch: Q, K, V as half (8 MB each) + transposed W as half (384 KB)
__device__ __half g_qh[BT*DD];
__device__ __half g_kh[BT*DD];
__device__ __half g_vh[BT*DD];
__device__ __half g_wth[192*1024];   // K-major: rows 0-63 Wq^T, 64-127 Wk^T, 128-191 Wv^T

// ===================== PTX helpers (sm_80+ PTX, ok on compute_103) =========
__device__ __forceinline__ void mma_f16_16n8k16(
    float d[4], const uint32_t a[4], const uint32_t b[2])
{
    asm volatile(
        "mma.sync.aligned.m16n8k16.row.col.f32.f16.f16.f32 "
        "{%0,%1,%2,%3}, {%4,%5,%6,%7}, {%8,%9}, {%0,%1,%2,%3};"
        : "+f"(d[0]), "+f"(d[1]), "+f"(d[2]), "+f"(d[3])
        : "r"(a[0]), "r"(a[1]), "r"(a[2]), "r"(a[3]),
          "r"(b[0]), "r"(b[1]));
}

__device__ __forceinline__ void ldmatrix_x4(uint32_t r[4], uint32_t addr) {
    asm volatile("ldmatrix.sync.aligned.m8n8.x4.shared.b16 {%0,%1,%2,%3}, [%4];"
        : "=r"(r[0]), "=r"(r[1]), "=r"(r[2]), "=r"(r[3]) : "r"(addr));
}

__device__ __forceinline__ void ldmatrix_x4_trans(uint32_t r[4], uint32_t addr) {
    asm volatile("ldmatrix.sync.aligned.m8n8.x4.trans.shared.b16 {%0,%1,%2,%3}, [%4];"
        : "=r"(r[0]), "=r"(r[1]), "=r"(r[2]), "=r"(r[3]) : "r"(addr));
}

__device__ __forceinline__ void cp_async16(uint32_t dst, const void* src) {
    asm volatile("cp.async.cg.shared.global [%0], [%1], 16;"
        :: "r"(dst), "l"(src) : "memory");
}
#define CP_COMMIT() asm volatile("cp.async.commit_group;" ::: "memory")
#define CP_WAIT1()  asm volatile("cp.async.wait_group 1;" ::: "memory")
#define CP_WAIT0()  asm volatile("cp.async.wait_group 0;" ::: "memory")

__device__ __forceinline__ uint32_t smem_u32(const void* p) {
    uint32_t a;
    asm("{ .reg .u64 t; cvta.to.shared.u64 t, %1; cvt.u32.u64 %0, t; }"
        : "=r"(a) : "l"(p));
    return a;
}

__device__ __forceinline__ uint32_t pack_h2(float a, float b) {
    half2 h = __floats2half2_rn(a, b);
    return *(uint32_t*)&h;
}

// ===================== Kernel 0: coalesced tile-transpose of W =============
__global__ __launch_bounds__(256) void transpose_w_kernel(
    const float* __restrict__ Wq, const float* __restrict__ Wk,
    const float* __restrict__ Wv)
{
    __shared__ float tile[64][65];
    const int m  = blockIdx.x >> 4;          // 0..2
    const int kt = blockIdx.x & 15;          // 0..15
    const float* W = (m == 0) ? Wq : (m == 1) ? Wk : Wv;

    const int r   = threadIdx.x >> 2;        // 0..63
    const int seg = threadIdx.x & 3;         // 0..3 (16 floats each)
    #pragma unroll
    for (int l = 0; l < 4; l++) {
        float4 v = *(const float4*)&W[(size_t)(kt * 64 + r) * 64 + seg * 16 + l * 4];
        tile[r][seg * 16 + l * 4 + 0] = v.x;
        tile[r][seg * 16 + l * 4 + 1] = v.y;
        tile[r][seg * 16 + l * 4 + 2] = v.z;
        tile[r][seg * 16 + l * 4 + 3] = v.w;
    }
    __syncthreads();

    const int n = r;
    uint32_t u[8];
    #pragma unroll
    for (int i = 0; i < 8; i++)
        u[i] = pack_h2(tile[seg * 16 + 2 * i][n], tile[seg * 16 + 2 * i + 1][n]);
    char* dst = (char*)&g_wth[(size_t)(m * 64 + n) * 1024 + kt * 64 + seg * 16];
    *(uint4*)dst        = make_uint4(u[0], u[1], u[2], u[3]);
    *(uint4*)(dst + 16) = make_uint4(u[4], u[5], u[6], u[7]);
}

// ===================== Kernel A: QKV via fp16 mma (R12/R9 version) =========
#define STRH 72
#define QA_BYTES (64*STRH*2)                   // 9216
#define QB_OFF   QA_BYTES
#define QCHUNK   (QA_BYTES + 192*STRH*2)       // 36864
#define QKV_SMEM (2*QCHUNK)                    // 73728

__global__ __launch_bounds__(256, 2) void qkv_mma_kernel(const float* __restrict__ x)
{
    extern __shared__ __half smh[];
    const uint32_t sbase = smem_u32(smh);
    const int tid    = threadIdx.x;
    const int lane   = tid & 31;
    const int wid    = tid >> 5;
    const int warp_m = wid >> 2;
    const int warp_n = wid & 3;
    const int row0   = blockIdx.x * 64;

    const int lr = lane >> 2;
    const int lc = lane & 3;

    float acc[2][6][4];
    #pragma unroll
    for (int mt = 0; mt < 2; mt++)
        #pragma unroll
        for (int nt = 0; nt < 6; nt++)
            #pragma unroll
            for (int i = 0; i < 4; i++) acc[mt][nt][i] = 0.f;

    const int ar   = tid >> 2;
    const int aseg = tid & 3;

    float4 ra[4];
    auto ldg_a = [&](int c) {
        const float* src = &x[(size_t)(row0 + ar) * CC + c * 64 + aseg * 16];
        #pragma unroll
        for (int l = 0; l < 4; l++) ra[l] = *(const float4*)(src + l * 4);
    };
    auto sts_a = [&](uint32_t bufoff) {
        char* dst = (char*)smh + bufoff + ((uint32_t)(ar * STRH + aseg * 16)) * 2;
        uint4 u0 = make_uint4(pack_h2(ra[0].x, ra[0].y), pack_h2(ra[0].z, ra[0].w),
                              pack_h2(ra[1].x, ra[1].y), pack_h2(ra[1].z, ra[1].w));
        uint4 u1 = make_uint4(pack_h2(ra[2].x, ra[2].y), pack_h2(ra[2].z, ra[2].w),
                              pack_h2(ra[3].x, ra[3].y), pack_h2(ra[3].z, ra[3].w));
        *(uint4*)dst = u0;
        *(uint4*)(dst + 16) = u1;
    };
    auto cp_b = [&](int c, uint32_t bufoff) {
        #pragma unroll
        for (int l = 0; l < 6; l++) {
            int idx = tid + l * 256;
            int n   = idx >> 3;
            int sg  = idx & 7;
            cp_async16(sbase + bufoff + QB_OFF + (uint32_t)(n * STRH + sg * 8) * 2,
                       &g_wth[(size_t)n * 1024 + c * 64 + sg * 8]);
        }
    };

    const uint32_t aoff =
        ((uint32_t)(warp_m * 32 + (lane & 7) + ((lane >> 3) & 1) * 8) * STRH
         + ((lane >> 4) & 1) * 8) * 2;
    const uint32_t boff = QB_OFF +
        ((uint32_t)(warp_n * 48 + (lane & 7) + ((lane >> 4) & 1) * 8) * STRH
         + ((lane >> 3) & 1) * 8) * 2;

    ldg_a(0); sts_a(0);
    cp_b(0, 0);        CP_COMMIT();
    cp_b(1, QCHUNK);   CP_COMMIT();
    ldg_a(1);

    for (int c = 0; c < 16; c++) {
        CP_WAIT1();
        __syncthreads();

        const uint32_t bufoff = (uint32_t)(c & 1) * QCHUNK;
        const uint32_t abase  = sbase + bufoff + aoff;
        const uint32_t bbase  = sbase + bufoff + boff;

        #pragma unroll
        for (int ks = 0; ks < 4; ks++) {
            uint32_t af[2][4];
            #pragma unroll
            for (int mt = 0; mt < 2; mt++)
                ldmatrix_x4(af[mt], abase + mt * (16 * STRH * 2) + ks * 32);
            uint32_t bf[12];
            #pragma unroll
            for (int j = 0; j < 3; j++)
                ldmatrix_x4(&bf[j * 4], bbase + j * (16 * STRH * 2) + ks * 32);
            #pragma unroll
            for (int mt = 0; mt < 2; mt++)
                #pragma unroll
                for (int nt = 0; nt < 6; nt++)
                    mma_f16_16n8k16(acc[mt][nt], af[mt],
                                    &bf[(nt >> 1) * 4 + (nt & 1) * 2]);
        }

        if (c + 1 < 16) {
            sts_a((uint32_t)((c + 1) & 1) * QCHUNK);
            if (c + 2 < 16) ldg_a(c + 2);
        }
        __syncthreads();

        if (c + 2 < 16) cp_b(c + 2, bufoff);
        CP_COMMIT();
    }

    #pragma unroll
    for (int mt = 0; mt < 2; mt++) {
        int rg = row0 + warp_m * 32 + mt * 16 + lr;
        #pragma unroll
        for (int nt = 0; nt < 6; nt++) {
            int ng = warp_n * 48 + nt * 8 + lc * 2;
            int m  = ng >> 6;
            int d  = ng & 63;
            __half* base = (m == 0) ? g_qh : (m == 1) ? g_kh : g_vh;
            *(uint32_t*)&base[(size_t)rg * DD + d] =
                pack_h2(acc[mt][nt][0], acc[mt][nt][1]);
            *(uint32_t*)&base[(size_t)(rg + 8) * DD + d] =
                pack_h2(acc[mt][nt][2], acc[mt][nt][3]);
        }
    }
}

// ===================== Kernel B: attention, warp-independent ===============
// Grid 256 (one CTA per batch), 8 warps. Each warp owns 32 q-rows (2 m-tiles
// of 16) over ALL keys: full row sums in-warp (quad shuffle only), no cross-
// warp reduction, no sO, ONE sync total. QK^T+exp+PV interleaved per 16-key
// group (P lives 4 regs). smem = K + V = 73728 -> 2 CTAs/SM.
#define KSTR 72
#define SKB  0
#define SVB  (256*KSTR*2)                  // 36864
#define ATT_SMEM (2*256*KSTR*2)            // 73728

__global__ __launch_bounds__(256, 2) void attn_kernel(float* __restrict__ out)
{
    extern __shared__ __half smh[];
    const uint32_t sbase = smem_u32(smh);

    const int tid  = threadIdx.x;
    const int wid  = tid >> 5;
    const int lane = tid & 31;
    const int lr   = lane >> 2;
    const int lc   = lane & 3;

    const int bb = blockIdx.x;          // batch

    // ---- stage full K, V once ----
    const __half* kb = g_kh + (size_t)bb * TT * DD;
    const __half* vb = g_vh + (size_t)bb * TT * DD;
    #pragma unroll
    for (int l = 0; l < 8; l++) {
        int idx = tid + l * 256;        // 0..2047
        int s   = idx >> 3;
        int sg  = idx & 7;
        cp_async16(sbase + SKB + (uint32_t)(s * KSTR + sg * 8) * 2,
                   &kb[s * DD + sg * 8]);
        cp_async16(sbase + SVB + (uint32_t)(s * KSTR + sg * 8) * 2,
                   &vb[s * DD + sg * 8]);
    }
    CP_COMMIT();

    // lane-constant ldmatrix bases (group offset added per 16-key group)
    const uint32_t kbase = sbase + SKB +
        ((uint32_t)((lane & 7) + ((lane >> 4) & 1) * 8) * KSTR
         + ((lane >> 3) & 1) * 8) * 2;
    const uint32_t vbase = sbase + SVB +
        ((uint32_t)((lane & 7) + ((lane >> 3) & 1) * 8) * KSTR
         + ((lane >> 4) & 1) * 8) * 2;

    const float SC = 0.03125f;          // C^-0.5

    CP_WAIT0();
    __syncthreads();                    // the only barrier

    #pragma unroll
    for (int mt = 0; mt < 2; mt++) {
        const int rb  = wid * 32 + mt * 16;   // this warp's 16-row tile base
        const int rg0 = rb + lr;
        const int rg1 = rg0 + 8;
        const int ng  = (rb >> 4) + 1;        // 16-key groups needed (causal)

        // ---- Q fragments (gmem, L2-hot) ----
        uint32_t qf[4][4];
        {
            const uint32_t* q32 =
                (const uint32_t*)(g_qh + (size_t)(bb * TT + rb + lr) * DD);
            const uint32_t* q32b = q32 + 8 * 32;          // row + 8
            #pragma unroll
            for (int ks = 0; ks < 4; ks++) {
                qf[ks][0] = q32 [ks * 8 + lc];
                qf[ks][1] = q32b[ks * 8 + lc];
                qf[ks][2] = q32 [ks * 8 + lc + 4];
                qf[ks][3] = q32b[ks * 8 + lc + 4];
            }
        }

        float srow[2] = {0.f, 0.f};
        float oacc[8][4];
        #pragma unroll
        for (int nt = 0; nt < 8; nt++)
            #pragma unroll
            for (int i = 0; i < 4; i++) oacc[nt][i] = 0.f;

        for (int g = 0; g < ng; g++) {
            // ---- QK^T for this 16-key group ----
            float s0[4] = {0.f, 0.f, 0.f, 0.f};
            float s1[4] = {0.f, 0.f, 0.f, 0.f};
            #pragma unroll
            for (int ks = 0; ks < 4; ks++) {
                uint32_t bf[4];
                ldmatrix_x4(bf, kbase + g * (16 * KSTR * 2) + ks * 32);
                mma_f16_16n8k16(s0, qf[ks], &bf[0]);
                mma_f16_16n8k16(s1, qf[ks], &bf[2]);
            }

            // ---- exp + causal mask, P packed in 4 regs ----
            const int cb = g * 16 + 2 * lc;
            float e00 = (cb     <= rg0) ? __expf(s0[0] * SC) : 0.f;
            float e01 = (cb + 1 <= rg0) ? __expf(s0[1] * SC) : 0.f;
            float e02 = (cb     <= rg1) ? __expf(s0[2] * SC) : 0.f;
            float e03 = (cb + 1 <= rg1) ? __expf(s0[3] * SC) : 0.f;
            float e10 = (cb + 8 <= rg0) ? __expf(s1[0] * SC) : 0.f;
            float e11 = (cb + 9 <= rg0) ? __expf(s1[1] * SC) : 0.f;
            float e12 = (cb + 8 <= rg1) ? __expf(s1[2] * SC) : 0.f;
            float e13 = (cb + 9 <= rg1) ? __expf(s1[3] * SC) : 0.f;
            srow[0] += e00 + e01 + e10 + e11;
            srow[1] += e02 + e03 + e12 + e13;
            uint32_t pf[4];
            pf[0] = pack_h2(e00, e01);
            pf[1] = pack_h2(e02, e03);
            pf[2] = pack_h2(e10, e11);
            pf[3] = pack_h2(e12, e13);

            // ---- PV for the same group ----
            #pragma unroll
            for (int pr = 0; pr < 4; pr++) {
                uint32_t bf[4];
                ldmatrix_x4_trans(bf, vbase + g * (16 * KSTR * 2) + pr * 32);
                mma_f16_16n8k16(oacc[2*pr],     pf, &bf[0]);
                mma_f16_16n8k16(oacc[2*pr + 1], pf, &bf[2]);
            }
        }

        // ---- full row sums (quad = whole row: this warp covers all keys) ----
        #pragma unroll
        for (int off = 1; off <= 2; off <<= 1) {
            srow[0] += __shfl_xor_sync(0xFFFFFFFF, srow[0], off);
            srow[1] += __shfl_xor_sync(0xFFFFFFFF, srow[1], off);
        }
        const float inv0 = 1.f / srow[0];
        const float inv1 = 1.f / srow[1];

        // ---- normalize + write output directly ----
        const size_t orow = (size_t)(bb * TT + rb + lr) * DD;
        #pragma unroll
        for (int nt = 0; nt < 8; nt++) {
            *(float2*)&out[orow + nt * 8 + 2 * lc] =
                make_float2(oacc[nt][0] * inv0, oacc[nt][1] * inv0);
            *(float2*)&out[orow + 8 * DD + nt * 8 + 2 * lc] =
                make_float2(oacc[nt][2] * inv1, oacc[nt][3] * inv1);
        }
    }
}

// ---------------------------------------------------------------------------
extern "C" void kernel_launch(void* const* d_in, const int* in_sizes, int n_in,
                              void* d_out, int out_size)
{
    (void)in_sizes; (void)n_in; (void)out_size;
    const float* x  = (const float*)d_in[0];
    const float* Wq = (const float*)d_in[1];
    const float* Wk = (const float*)d_in[2];
    const float* Wv = (const float*)d_in[3];
    float* out = (float*)d_out;

    cudaFuncSetAttribute(qkv_mma_kernel,
                         cudaFuncAttributeMaxDynamicSharedMemorySize, QKV_SMEM);
    cudaFuncSetAttribute(attn_kernel,
                         cudaFuncAttributeMaxDynamicSharedMemorySize, ATT_SMEM);

    transpose_w_kernel<<<48, 256>>>(Wq, Wk, Wv);
    qkv_mma_kernel<<<BT / 64, 256, QKV_SMEM>>>(x);
    attn_kernel<<<BB, 256, ATT_SMEM>>>(out);
}